// round 1
// baseline (speedup 1.0000x reference)
#include <cuda_runtime.h>
#include <math.h>

#define VOX   4096
#define TPTS  100
#define KNN   8

// BN-folded weights: wa[c][o] = w1[o][c]*scale[o]; wb[c][o] = (w2[o][c]-w1[o][c])*scale[o]
__device__ float g_wa[9 * 64];
__device__ float g_wb[9 * 64];
__device__ float g_bias[64];

__global__ void prep_kernel(const float* __restrict__ conv_w,
                            const float* __restrict__ gamma,
                            const float* __restrict__ beta,
                            const float* __restrict__ mean,
                            const float* __restrict__ var) {
    int o = threadIdx.x;
    if (o >= 64) return;
    float scale = gamma[o] / sqrtf(var[o] + 1e-3f);
#pragma unroll
    for (int c = 0; c < 9; c++) {
        float w1 = conv_w[o * 18 + c];
        float w2 = conv_w[o * 18 + 9 + c];
        g_wa[c * 64 + o] = w1 * scale;
        g_wb[c * 64 + o] = (w2 - w1) * scale;
    }
    g_bias[o] = beta[o] - mean[o] * scale;
}

__device__ __forceinline__ float4 dot9x4(const float (*w)[64], int o4,
                                         float4 fa, float4 fb, float f8, float4 acc) {
    float fs[9] = {fa.x, fa.y, fa.z, fa.w, fb.x, fb.y, fb.z, fb.w, f8};
#pragma unroll
    for (int c = 0; c < 9; c++) {
        float4 wv = *reinterpret_cast<const float4*>(&w[c][o4 * 4]);
        acc.x = fmaf(fs[c], wv.x, acc.x);
        acc.y = fmaf(fs[c], wv.y, acc.y);
        acc.z = fmaf(fs[c], wv.z, acc.z);
        acc.w = fmaf(fs[c], wv.w, acc.w);
    }
    return acc;
}

__global__ __launch_bounds__(128) void gcn_kernel(
    const float* __restrict__ features,   // [4096,100,4]
    const int*   __restrict__ num_voxels, // [4096]
    const int*   __restrict__ coors,      // [4096,4]
    float*       __restrict__ out)        // [4096,64]
{
    __shared__ __align__(16) float s_feat[TPTS][12];   // 9 feat, [9]=xx, [10..11]=0
    __shared__ __align__(16) float s_a[TPTS][64];      // a' = (feat@w1)*scale
    __shared__ __align__(16) float s_wa[9][64];
    __shared__ __align__(16) float s_wb[9][64];
    __shared__ __align__(16) float s_bias[64];
    __shared__ int   s_idx[TPTS][KNN];
    __shared__ float s_red[3][128];
    __shared__ __align__(16) float s_part[8][64];
    __shared__ float s_mean[3];

    const int tid = threadIdx.x;
    const int vox = blockIdx.x;
    int nv = num_voxels[vox];
    if (nv > TPTS) nv = TPTS;

    // ---- copy folded weights to smem ----
    for (int i = tid; i < 9 * 64; i += 128) {
        (&s_wa[0][0])[i] = g_wa[i];
        (&s_wb[0][0])[i] = g_wb[i];
    }
    if (tid < 64) s_bias[tid] = g_bias[tid];

    // ---- phase 1: load features, reduce mean of first 3 channels over all T ----
    float4 fv = make_float4(0.f, 0.f, 0.f, 0.f);
    if (tid < TPTS)
        fv = reinterpret_cast<const float4*>(features)[vox * TPTS + tid];
    s_red[0][tid] = (tid < TPTS) ? fv.x : 0.f;
    s_red[1][tid] = (tid < TPTS) ? fv.y : 0.f;
    s_red[2][tid] = (tid < TPTS) ? fv.z : 0.f;
    __syncthreads();
#pragma unroll
    for (int s = 64; s > 0; s >>= 1) {
        if (tid < s) {
            s_red[0][tid] += s_red[0][tid + s];
            s_red[1][tid] += s_red[1][tid + s];
            s_red[2][tid] += s_red[2][tid + s];
        }
        __syncthreads();
    }
    if (tid == 0) {
        float fnv = (float)nv;
        s_mean[0] = s_red[0][0] / fnv;
        s_mean[1] = s_red[1][0] / fnv;
        s_mean[2] = s_red[2][0] / fnv;
    }
    __syncthreads();

    // ---- build masked 9-channel feat + xx ----
    const float cx = (float)coors[vox * 4 + 3] * 0.2f + 0.1f;
    const float cy = (float)coors[vox * 4 + 2] * 0.2f + (-39.9f);
    if (tid < TPTS) {
        float m  = (tid < nv) ? 1.0f : 0.0f;
        float f[9];
        f[0] = fv.x * m;  f[1] = fv.y * m;  f[2] = fv.z * m;  f[3] = fv.w * m;
        f[4] = (fv.x - s_mean[0]) * m;
        f[5] = (fv.y - s_mean[1]) * m;
        f[6] = (fv.z - s_mean[2]) * m;
        f[7] = (fv.x - cx) * m;
        f[8] = (fv.y - cy) * m;
        float xx = 0.f;
#pragma unroll
        for (int c = 0; c < 9; c++) xx = fmaf(f[c], f[c], xx);
#pragma unroll
        for (int c = 0; c < 9; c++) s_feat[tid][c] = f[c];
        s_feat[tid][9]  = xx;
        s_feat[tid][10] = 0.f;
        s_feat[tid][11] = 0.f;
    }
    __syncthreads();

    // ---- phase 2: a'[t][o] = (feat[t] . w1[:,o]) * scale[o]  (BN scale folded in s_wa)
    for (int p = tid; p < TPTS * 16; p += 128) {
        int t  = p >> 4;
        int o4 = p & 15;
        const float4* fr = reinterpret_cast<const float4*>(s_feat[t]);
        float4 fa = fr[0], fb = fr[1];
        float  f8 = s_feat[t][8];
        float4 acc = make_float4(0.f, 0.f, 0.f, 0.f);
        acc = dot9x4(s_wa, o4, fa, fb, f8, acc);
        *reinterpret_cast<float4*>(&s_a[t][o4 * 4]) = acc;
    }
    __syncthreads();

    // ---- phase 3: per-point top-8 neighbors by neg_dist = 2*inner - xx_t - xx_j ----
    if (tid < nv) {
        const float4* mr = reinterpret_cast<const float4*>(s_feat[tid]);
        float4 fa = mr[0], fb = mr[1];
        float4 fc = mr[2];                 // x: f8, y: xx_t
        float  f8 = fc.x, xxt = fc.y;

        float v[KNN];
        int   id[KNN];
#pragma unroll
        for (int k = 0; k < KNN; k++) { v[k] = -3.402823466e38f; id[k] = 0; }

        for (int j = 0; j < TPTS; j++) {
            const float4* jr = reinterpret_cast<const float4*>(s_feat[j]);
            float4 ja = jr[0], jb = jr[1], jc = jr[2];
            float inner = 0.f;
            inner = fmaf(fa.x, ja.x, inner);
            inner = fmaf(fa.y, ja.y, inner);
            inner = fmaf(fa.z, ja.z, inner);
            inner = fmaf(fa.w, ja.w, inner);
            inner = fmaf(fb.x, jb.x, inner);
            inner = fmaf(fb.y, jb.y, inner);
            inner = fmaf(fb.z, jb.z, inner);
            inner = fmaf(fb.w, jb.w, inner);
            inner = fmaf(f8,   jc.x, inner);
            float d = (2.0f * inner - xxt) - jc.y;
            if (d > v[KNN - 1]) {          // strict >: ties keep lowest index (jax semantics)
                v[KNN - 1] = d; id[KNN - 1] = j;
#pragma unroll
                for (int s = KNN - 1; s > 0; --s) {
                    if (v[s] > v[s - 1]) {
                        float tv = v[s]; v[s] = v[s - 1]; v[s - 1] = tv;
                        int   ti = id[s]; id[s] = id[s - 1]; id[s - 1] = ti;
                    }
                }
            }
        }
#pragma unroll
        for (int k = 0; k < KNN; k++) s_idx[tid][k] = id[k];
    }
    __syncthreads();

    // ---- phase 4: out[t] = lrelu(max_k a'[idx] + b'[t]); final = max(0, max_t) ----
    {
        int o4    = tid & 15;
        int slice = tid >> 4;     // 0..7
        float4 rmax = make_float4(0.f, 0.f, 0.f, 0.f);   // 0 floor from masked rows
        for (int t = slice; t < nv; t += 8) {
            float4 m4 = make_float4(-3.402823466e38f, -3.402823466e38f,
                                    -3.402823466e38f, -3.402823466e38f);
#pragma unroll
            for (int k = 0; k < KNN; k++) {
                int j = s_idx[t][k];
                float4 a = *reinterpret_cast<const float4*>(&s_a[j][o4 * 4]);
                m4.x = fmaxf(m4.x, a.x);
                m4.y = fmaxf(m4.y, a.y);
                m4.z = fmaxf(m4.z, a.z);
                m4.w = fmaxf(m4.w, a.w);
            }
            const float4* fr = reinterpret_cast<const float4*>(s_feat[t]);
            float4 fa = fr[0], fb = fr[1];
            float  f8 = s_feat[t][8];
            float4 b  = *reinterpret_cast<const float4*>(&s_bias[o4 * 4]);
            b = dot9x4(s_wb, o4, fa, fb, f8, b);

            float4 h;
            h.x = m4.x + b.x;  h.y = m4.y + b.y;  h.z = m4.z + b.z;  h.w = m4.w + b.w;
            h.x = (h.x >= 0.f) ? h.x : 0.2f * h.x;
            h.y = (h.y >= 0.f) ? h.y : 0.2f * h.y;
            h.z = (h.z >= 0.f) ? h.z : 0.2f * h.z;
            h.w = (h.w >= 0.f) ? h.w : 0.2f * h.w;
            rmax.x = fmaxf(rmax.x, h.x);
            rmax.y = fmaxf(rmax.y, h.y);
            rmax.z = fmaxf(rmax.z, h.z);
            rmax.w = fmaxf(rmax.w, h.w);
        }
        *reinterpret_cast<float4*>(&s_part[slice][o4 * 4]) = rmax;
    }
    __syncthreads();

    if (tid < 64) {
        float r = s_part[0][tid];
#pragma unroll
        for (int s = 1; s < 8; s++) r = fmaxf(r, s_part[s][tid]);
        out[vox * 64 + tid] = r;
    }
}

extern "C" void kernel_launch(void* const* d_in, const int* in_sizes, int n_in,
                              void* d_out, int out_size) {
    const float* features   = (const float*)d_in[0];
    const float* conv_w     = (const float*)d_in[1];
    const float* bn_gamma   = (const float*)d_in[2];
    const float* bn_beta    = (const float*)d_in[3];
    const float* bn_mean    = (const float*)d_in[4];
    const float* bn_var     = (const float*)d_in[5];
    const int*   num_voxels = (const int*)d_in[6];
    const int*   coors      = (const int*)d_in[7];
    float*       out        = (float*)d_out;

    prep_kernel<<<1, 64>>>(conv_w, bn_gamma, bn_beta, bn_mean, bn_var);
    gcn_kernel<<<VOX, 128>>>(features, num_voxels, coors, out);
}

// round 2
// speedup vs baseline: 1.2546x; 1.2546x over previous
#include <cuda_runtime.h>
#include <math.h>

#define VOX   4096
#define TPTS  100
#define KNN   8
#define NEG_INF (-3.402823466e38f)

// BN-folded weights: wa[c][o] = w1[o][c]*scale[o]; wb[c][o] = (w2[o][c]-w1[o][c])*scale[o]
__device__ __align__(16) float g_wa[9 * 64];
__device__ __align__(16) float g_wb[9 * 64];
__device__ __align__(16) float g_bias[64];

__global__ void prep_kernel(const float* __restrict__ conv_w,
                            const float* __restrict__ gamma,
                            const float* __restrict__ beta,
                            const float* __restrict__ mean,
                            const float* __restrict__ var) {
    int o = threadIdx.x;
    if (o >= 64) return;
    float scale = gamma[o] / sqrtf(var[o] + 1e-3f);
#pragma unroll
    for (int c = 0; c < 9; c++) {
        float w1 = conv_w[o * 18 + c];
        float w2 = conv_w[o * 18 + 9 + c];
        g_wa[c * 64 + o] = w1 * scale;
        g_wb[c * 64 + o] = (w2 - w1) * scale;
    }
    g_bias[o] = beta[o] - mean[o] * scale;
}

// branchless sorted-insert of (d, jj) into desc-sorted v/id[8], strict > (stable ties)
__device__ __forceinline__ void ins8(float v[KNN], int id[KNN], float d, int jj) {
#pragma unroll
    for (int s = 0; s < KNN; s++) {
        bool gt = d > v[s];
        float vs = v[s]; int is = id[s];
        v[s]  = gt ? d  : vs;
        id[s] = gt ? jj : is;
        d     = gt ? vs : d;
        jj    = gt ? is : jj;
    }
}

__global__ __launch_bounds__(128, 6) void gcn_kernel(
    const float* __restrict__ features,   // [4096,100,4]
    const int*   __restrict__ num_voxels, // [4096]
    const int*   __restrict__ coors,      // [4096,4]
    float*       __restrict__ out)        // [4096,64]
{
    __shared__ __align__(16) float s_feat[TPTS][12];  // 9 feat, [9]=xx
    __shared__ __align__(16) float s_a[TPTS * 64];    // a'; overlaid w/ topk candidates
    __shared__ __align__(16) float s_wb[9 * 64];
    __shared__ __align__(16) float s_bias[64];
    __shared__ unsigned char s_idx[TPTS][KNN];
    __shared__ __align__(16) float s_scr[512];        // warp sums / final partials
    __shared__ float s_mean[3];

    const int tid = threadIdx.x;
    const int vox = blockIdx.x;
    int nv = num_voxels[vox];
    if (nv < 1) nv = 1;
    if (nv > TPTS) nv = TPTS;

    // ---- weights to smem (wb hot in phase 4; wa stays in global/L1) ----
    for (int i = tid; i < 9 * 64; i += 128) s_wb[i] = g_wb[i];
    if (tid < 64) s_bias[tid] = g_bias[tid];

    // ---- phase 1: load + mean over first 3 channels (warp shuffles) ----
    float4 fv = make_float4(0.f, 0.f, 0.f, 0.f);
    if (tid < TPTS)
        fv = reinterpret_cast<const float4*>(features)[vox * TPTS + tid];
    float sx = (tid < TPTS) ? fv.x : 0.f;
    float sy = (tid < TPTS) ? fv.y : 0.f;
    float sz = (tid < TPTS) ? fv.z : 0.f;
#pragma unroll
    for (int o = 16; o > 0; o >>= 1) {
        sx += __shfl_down_sync(0xffffffffu, sx, o);
        sy += __shfl_down_sync(0xffffffffu, sy, o);
        sz += __shfl_down_sync(0xffffffffu, sz, o);
    }
    if ((tid & 31) == 0) {
        int w = tid >> 5;
        s_scr[w] = sx; s_scr[4 + w] = sy; s_scr[8 + w] = sz;
    }
    __syncthreads();
    if (tid == 0) {
        float fnv = (float)nv;
        s_mean[0] = (s_scr[0] + s_scr[1] + s_scr[2] + s_scr[3]) / fnv;
        s_mean[1] = (s_scr[4] + s_scr[5] + s_scr[6] + s_scr[7]) / fnv;
        s_mean[2] = (s_scr[8] + s_scr[9] + s_scr[10] + s_scr[11]) / fnv;
    }
    __syncthreads();

    const float cx = (float)coors[vox * 4 + 3] * 0.2f + 0.1f;
    const float cy = (float)coors[vox * 4 + 2] * 0.2f + (-39.9f);
    if (tid < TPTS) {
        float m = (tid < nv) ? 1.0f : 0.0f;
        float f[9];
        f[0] = fv.x * m;  f[1] = fv.y * m;  f[2] = fv.z * m;  f[3] = fv.w * m;
        f[4] = (fv.x - s_mean[0]) * m;
        f[5] = (fv.y - s_mean[1]) * m;
        f[6] = (fv.z - s_mean[2]) * m;
        f[7] = (fv.x - cx) * m;
        f[8] = (fv.y - cy) * m;
        float xx = 0.f;
#pragma unroll
        for (int c = 0; c < 9; c++) xx = fmaf(f[c], f[c], xx);
#pragma unroll
        for (int c = 0; c < 9; c++) s_feat[tid][c] = f[c];
        s_feat[tid][9]  = xx;
        s_feat[tid][10] = 0.f;
        s_feat[tid][11] = 0.f;
    }
    __syncthreads();

    // ---- phase 3: top-8 by key = 2*<xt,xj> - xx_j (per-t offset -xx_t dropped;
    //      masked candidates all have key == 0, handled analytically) ----
    float* candv = s_a;                       // [2*TPTS][8] values
    int*   candi = (int*)(s_a + 2 * TPTS * KNN); // [2*TPTS][8] ids
    const int h = nv >> 1;
    const int items = 2 * nv;
    for (int item = tid; item < items; item += 128) {
        int t    = item >> 1;
        int half = item & 1;
        int j0 = half ? h  : 0;
        int j1 = half ? nv : h;
        const float4* fr = reinterpret_cast<const float4*>(s_feat[t]);
        float4 fa = fr[0], fb = fr[1];
        float  f8 = s_feat[t][8];

        float v[KNN]; int id[KNN];
#pragma unroll
        for (int k = 0; k < KNN; k++) { v[k] = NEG_INF; id[k] = 0; }

#pragma unroll 2
        for (int j = j0; j < j1; j++) {
            const float* row = s_feat[j];
            float4 ja = reinterpret_cast<const float4*>(row)[0];
            float4 jb = reinterpret_cast<const float4*>(row)[1];
            float2 jc = *reinterpret_cast<const float2*>(row + 8);
            float inner = 0.f;
            inner = fmaf(fa.x, ja.x, inner);
            inner = fmaf(fa.y, ja.y, inner);
            inner = fmaf(fa.z, ja.z, inner);
            inner = fmaf(fa.w, ja.w, inner);
            inner = fmaf(fb.x, jb.x, inner);
            inner = fmaf(fb.y, jb.y, inner);
            inner = fmaf(fb.z, jb.z, inner);
            inner = fmaf(fb.w, jb.w, inner);
            inner = fmaf(f8,   jc.x, inner);
            float key = fmaf(2.0f, inner, -jc.y);
            ins8(v, id, key, j);
        }
#pragma unroll
        for (int k = 0; k < KNN; k++) {
            candv[item * KNN + k] = v[k];
            candi[item * KNN + k] = id[k];
        }
    }
    __syncthreads();

    // merge the two halves per point, then fill masked neighbors (key==0)
    if (tid < nv) {
        const int t = tid;
        float v[KNN]; int id[KNN];
#pragma unroll
        for (int k = 0; k < KNN; k++) {
            v[k]  = candv[(2 * t) * KNN + k];
            id[k] = candi[(2 * t) * KNN + k];
        }
#pragma unroll
        for (int k = 0; k < KNN; k++) {
            float d = candv[(2 * t + 1) * KNN + k];
            int  jj = candi[(2 * t + 1) * KNN + k];
            ins8(v, id, d, jj);
        }
        // masked points: indices nv..99, all key==0, ascending index order
        for (int jm = nv; jm < TPTS; jm++) {
            if (!(0.f > v[KNN - 1])) break;
            ins8(v, id, 0.f, jm);
        }
#pragma unroll
        for (int k = 0; k < KNN; k++) s_idx[t][k] = (unsigned char)id[k];
    }
    __syncthreads();

    // ---- phase 2: a'[t][o] = (feat[t] . wa[:,o]) — overwrites candidate overlay ----
    for (int p = tid; p < TPTS * 16; p += 128) {
        int t  = p >> 4;
        int o4 = p & 15;
        const float4* fr = reinterpret_cast<const float4*>(s_feat[t]);
        float4 fa = fr[0], fb = fr[1];
        float  f8 = s_feat[t][8];
        float fs[9] = {fa.x, fa.y, fa.z, fa.w, fb.x, fb.y, fb.z, fb.w, f8};
        float4 acc = make_float4(0.f, 0.f, 0.f, 0.f);
#pragma unroll
        for (int c = 0; c < 9; c++) {
            float4 wv = __ldg(reinterpret_cast<const float4*>(&g_wa[c * 64 + o4 * 4]));
            acc.x = fmaf(fs[c], wv.x, acc.x);
            acc.y = fmaf(fs[c], wv.y, acc.y);
            acc.z = fmaf(fs[c], wv.z, acc.z);
            acc.w = fmaf(fs[c], wv.w, acc.w);
        }
        reinterpret_cast<float4*>(s_a)[t * 16 + o4] = acc;
    }
    __syncthreads();

    // ---- phase 4: lrelu(max_k a'[idx]+b'[t]) then max over t with 0 floor ----
    {
        const int o4    = tid & 15;
        const int slice = tid >> 4;   // 0..7
        float4 rmax = make_float4(0.f, 0.f, 0.f, 0.f);
        for (int t = slice; t < nv; t += 8) {
            float4 m4 = make_float4(NEG_INF, NEG_INF, NEG_INF, NEG_INF);
#pragma unroll
            for (int k = 0; k < KNN; k++) {
                int j = (int)s_idx[t][k];
                float4 a = reinterpret_cast<const float4*>(s_a)[j * 16 + o4];
                m4.x = fmaxf(m4.x, a.x);
                m4.y = fmaxf(m4.y, a.y);
                m4.z = fmaxf(m4.z, a.z);
                m4.w = fmaxf(m4.w, a.w);
            }
            const float4* fr = reinterpret_cast<const float4*>(s_feat[t]);
            float4 fa = fr[0], fb = fr[1];
            float  f8 = s_feat[t][8];
            float fs[9] = {fa.x, fa.y, fa.z, fa.w, fb.x, fb.y, fb.z, fb.w, f8};
            float4 b = *reinterpret_cast<const float4*>(&s_bias[o4 * 4]);
#pragma unroll
            for (int c = 0; c < 9; c++) {
                float4 wv = *reinterpret_cast<const float4*>(&s_wb[c * 64 + o4 * 4]);
                b.x = fmaf(fs[c], wv.x, b.x);
                b.y = fmaf(fs[c], wv.y, b.y);
                b.z = fmaf(fs[c], wv.z, b.z);
                b.w = fmaf(fs[c], wv.w, b.w);
            }
            float4 hh;
            hh.x = m4.x + b.x;  hh.y = m4.y + b.y;
            hh.z = m4.z + b.z;  hh.w = m4.w + b.w;
            hh.x = (hh.x >= 0.f) ? hh.x : 0.2f * hh.x;
            hh.y = (hh.y >= 0.f) ? hh.y : 0.2f * hh.y;
            hh.z = (hh.z >= 0.f) ? hh.z : 0.2f * hh.z;
            hh.w = (hh.w >= 0.f) ? hh.w : 0.2f * hh.w;
            rmax.x = fmaxf(rmax.x, hh.x);
            rmax.y = fmaxf(rmax.y, hh.y);
            rmax.z = fmaxf(rmax.z, hh.z);
            rmax.w = fmaxf(rmax.w, hh.w);
        }
        reinterpret_cast<float4*>(s_scr)[slice * 16 + o4] = rmax;
    }
    __syncthreads();

    if (tid < 64) {
        float r = s_scr[tid];
#pragma unroll
        for (int s = 1; s < 8; s++) r = fmaxf(r, s_scr[s * 64 + tid]);
        out[vox * 64 + tid] = r;
    }
}

extern "C" void kernel_launch(void* const* d_in, const int* in_sizes, int n_in,
                              void* d_out, int out_size) {
    const float* features   = (const float*)d_in[0];
    const float* conv_w     = (const float*)d_in[1];
    const float* bn_gamma   = (const float*)d_in[2];
    const float* bn_beta    = (const float*)d_in[3];
    const float* bn_mean    = (const float*)d_in[4];
    const float* bn_var     = (const float*)d_in[5];
    const int*   num_voxels = (const int*)d_in[6];
    const int*   coors      = (const int*)d_in[7];
    float*       out        = (float*)d_out;

    prep_kernel<<<1, 64>>>(conv_w, bn_gamma, bn_beta, bn_mean, bn_var);
    gcn_kernel<<<VOX, 128>>>(features, num_voxels, coors, out);
}